// round 14
// baseline (speedup 1.0000x reference)
#include <cuda_runtime.h>
#include <cuda_bf16.h>
#include <stdint.h>

#define KCLS   64
#define QPC    128
#define DIMK   1024
#define NROWS  (KCLS * QPC)      // 8192
#define TMR    32                // rows per CTA
#define NCTA   (NROWS / TMR)     // 256
#define KC     64                // k elems per chunk
#define NCH    16                // chunks per modality
#define NCHT   48                // total chunks (3 modalities)

// ---------------- smem layout (bytes), stride-72 bf16 rows (144B) -----------
#define A_STR   72
#define OFF_AH  0
#define OFF_AL  4608
#define OFF_BH  9216
#define OFF_BL  18432
#define BUFSZ   27648
#define NSTAGE  3
#define OFF_SL   (NSTAGE * BUFSZ)            // 82944, 32 x 72 fp32
#define SL_STR   72
#define OFF_PRED (OFF_SL + 9216)             // 92160, 32 x 68 fp32
#define PRED_STR 68
#define OFF_SX2  (OFF_PRED + 8704)           // 100864
#define OFF_SP2  (OFF_SX2 + 128)
#define OFF_SRV  (OFF_SP2 + 256)
#define OFF_RED  (OFF_SRV + 256)
#define SMEM_TOTAL (OFF_RED + 64)            // 101568 -> 2 CTAs/SM

// named barrier ids
#define BID_FULL   1   // 1..3
#define BID_EMPTY  4   // 4..6
#define BID_X2     7
#define BID_CONS   8

__device__ float  g_p2[3][KCLS];
__device__ float  g_rvar[3][KCLS];
__device__ float2 g_part[NCTA];
__device__ int    g_done;
// pre-split protos: flat [chunk(48)][row(64)][8 uint4] (row = 64 bf16 = 128 B)
__device__ uint4  g_Bh2[NCHT * KCLS * 8];
__device__ uint4  g_Bl2[NCHT * KCLS * 8];

// ---------------------------------------------------------------------------
__device__ __forceinline__ uint32_t smem_u32(const void* p) {
    uint32_t a;
    asm("{ .reg .u64 t; cvta.to.shared.u64 t, %1; cvt.u32.u64 %0, t; }" : "=r"(a) : "l"(p));
    return a;
}
__device__ __forceinline__ void cp16(uint32_t dst, const void* src) {
    asm volatile("cp.async.cg.shared.global [%0], [%1], 16;" :: "r"(dst), "l"(src) : "memory");
}
#define CP_COMMIT() asm volatile("cp.async.commit_group;" ::: "memory")
#define CP_WAIT0()  asm volatile("cp.async.wait_group 0;" ::: "memory")
#define CP_WAIT1()  asm volatile("cp.async.wait_group 1;" ::: "memory")
#define CP_WAIT2()  asm volatile("cp.async.wait_group 2;" ::: "memory")

#define BSYNC(id, n) asm volatile("bar.sync %0, %1;"   :: "r"(id), "r"(n) : "memory")
#define BARRV(id, n) asm volatile("bar.arrive %0, %1;" :: "r"(id), "r"(n) : "memory")

__device__ __forceinline__ void ldsm4(uint32_t* r, uint32_t a) {
    asm volatile("ldmatrix.sync.aligned.m8n8.x4.shared.b16 {%0,%1,%2,%3}, [%4];"
                 : "=r"(r[0]), "=r"(r[1]), "=r"(r[2]), "=r"(r[3]) : "r"(a));
}
__device__ __forceinline__ void mma_bf16(float c[4], const uint32_t a[4], const uint32_t b[2]) {
    asm volatile(
        "mma.sync.aligned.m16n8k16.row.col.f32.bf16.bf16.f32 "
        "{%0,%1,%2,%3}, {%4,%5,%6,%7}, {%8,%9}, {%0,%1,%2,%3};\n"
        : "+f"(c[0]), "+f"(c[1]), "+f"(c[2]), "+f"(c[3])
        : "r"(a[0]), "r"(a[1]), "r"(a[2]), "r"(a[3]), "r"(b[0]), "r"(b[1]));
}

// fp32x8 -> bf16 hi + bf16 lo
__device__ __forceinline__ void split8(float4 a, float4 b, uint4& hi, uint4& lo) {
    float f[8] = {a.x, a.y, a.z, a.w, b.x, b.y, b.z, b.w};
    uint32_t hw[4], lw[4];
    #pragma unroll
    for (int i = 0; i < 4; i++) {
        __nv_bfloat162 h = __floats2bfloat162_rn(f[2*i], f[2*i+1]);
        float r0 = f[2*i]     - __bfloat162float(h.x);
        float r1 = f[2*i + 1] - __bfloat162float(h.y);
        __nv_bfloat162 l = __floats2bfloat162_rn(r0, r1);
        hw[i] = *reinterpret_cast<uint32_t*>(&h);
        lw[i] = *reinterpret_cast<uint32_t*>(&l);
    }
    hi = make_uint4(hw[0], hw[1], hw[2], hw[3]);
    lo = make_uint4(lw[0], lw[1], lw[2], lw[3]);
}
__device__ __forceinline__ float sq8(float4 a, float4 b) {
    return a.x*a.x + a.y*a.y + a.z*a.z + a.w*a.w
         + b.x*b.x + b.y*b.y + b.z*b.z + b.w*b.w;
}

// ---------------------------------------------------------------------------
// prep: p2, 1/var, pre-split protos into chunk-major bf16 hi/lo (KC=64 rows)
// ---------------------------------------------------------------------------
__global__ void prep_kernel(const float* __restrict__ pTF, const float* __restrict__ vTF,
                            const float* __restrict__ pDE, const float* __restrict__ vDE,
                            const float* __restrict__ pFFT, const float* __restrict__ vFFT)
{
    __shared__ float red[4];
    const int b = blockIdx.x;
    const int m = b >> 6, j = b & 63;
    const int tid = threadIdx.x;

    const float* P = (m == 0 ? pTF : (m == 1 ? pDE : pFFT)) + (size_t)j * DIMK;
    const int c0 = tid * 8;
    float4 x0 = *reinterpret_cast<const float4*>(P + c0);
    float4 x1 = *reinterpret_cast<const float4*>(P + c0 + 4);
    float s = sq8(x0, x1);

    uint4 hi, lo; split8(x0, x1, hi, lo);
    const int chunk = c0 >> 6;
    const int col   = c0 & 63;
    const size_t idx = (((size_t)(m * NCH + chunk) * KCLS) + j) * 8 + (col >> 3);
    g_Bh2[idx] = hi;
    g_Bl2[idx] = lo;

    #pragma unroll
    for (int o = 16; o > 0; o >>= 1) s += __shfl_xor_sync(0xffffffffu, s, o);
    if ((tid & 31) == 0) red[tid >> 5] = s;
    __syncthreads();
    if (tid == 0) {
        g_p2[m][j] = red[0] + red[1] + red[2] + red[3];
        const float* V = (m == 0 ? vTF : (m == 1 ? vDE : vFFT));
        g_rvar[m][j] = 1.0f / V[j];
    }
}

// ---------------------------------------------------------------------------
// warp-specialized fused kernel: 4 producer warps (LDG+split A, cp.async B),
// 4 consumer warps (m32n16 HMMA), named-barrier stage ring, per-modality
// softmax/loss epilogue, last-CTA reduction. 256 CTAs x 256 threads.
// ---------------------------------------------------------------------------
__global__ void __launch_bounds__(256, 2)
fusion_kernel(const float* __restrict__ xTF, const float* __restrict__ xDE,
              const float* __restrict__ xFFT, float* __restrict__ out, int out_size)
{
    extern __shared__ unsigned char smemc[];
    __shared__ int sLast;
    const uint32_t sb = smem_u32(smemc);

    const int tid  = threadIdx.x;
    const int warp = tid >> 5;
    const int lane = tid & 31;
    const int cls  = (int)(blockIdx.x >> 2);
    const size_t rowbase = (size_t)blockIdx.x * TMR;

    float* sL   = reinterpret_cast<float*>(smemc + OFF_SL);
    float* sPrd = reinterpret_cast<float*>(smemc + OFF_PRED);
    float* sX2  = reinterpret_cast<float*>(smemc + OFF_SX2);
    float* sP2  = reinterpret_cast<float*>(smemc + OFF_SP2);
    float* sRv  = reinterpret_cast<float*>(smemc + OFF_SRV);
    float* sBL  = reinterpret_cast<float*>(smemc + OFF_RED);
    int*   sBA  = reinterpret_cast<int*>(smemc + OFF_RED + 4);

    if (tid == 0) { *sBL = 0.0f; *sBA = 0; }
    for (int i = tid; i < 32 * PRED_STR; i += 256) sPrd[i] = 0.0f;
    __syncthreads();

    const float wts[3] = {1.0f, 0.8f, 0.6f};

    if (warp >= 4) {
        // ==================== PRODUCER (warps 4-7) ====================
        const int ptid = tid - 128;
        const int prow = ptid >> 2;
        const int pcb  = (ptid & 3) * 16;           // fp32 col base
        const uint32_t aoff = (uint32_t)(prow * 144 + pcb * 2);
        float x2acc = 0.0f;
        float4 a0, a1, a2, a3, n0, n1, n2, n3;

        // prologue: B[0]->st0, B[1]->st1 (two groups), A[0] regs
        #pragma unroll
        for (int c = 0; c < 2; c++) {
            const uint4* H = g_Bh2 + (size_t)c * 512;
            const uint4* L = g_Bl2 + (size_t)c * 512;
            #pragma unroll
            for (int q = 0; q < 4; q++) {
                const int s = ptid + 128 * q;
                const uint32_t d = (uint32_t)(c * BUFSZ + (s >> 3) * 144 + (s & 7) * 16);
                cp16(sb + OFF_BH + d, H + s);
                cp16(sb + OFF_BL + d, L + s);
            }
            CP_COMMIT();
        }
        {
            const float* p = xTF + (rowbase + prow) * DIMK + pcb;
            a0 = *reinterpret_cast<const float4*>(p);
            a1 = *reinterpret_cast<const float4*>(p + 4);
            a2 = *reinterpret_cast<const float4*>(p + 8);
            a3 = *reinterpret_cast<const float4*>(p + 12);
        }

        for (int gi = 0; gi < NCHT; gi++) {
            const int st = gi % 3;
            const int c2 = gi + 2;
            if (c2 < NCHT) {
                if (c2 >= 3) BSYNC(BID_EMPTY + c2 % 3, 256);
                const uint4* H = g_Bh2 + (size_t)c2 * 512;
                const uint4* L = g_Bl2 + (size_t)c2 * 512;
                #pragma unroll
                for (int q = 0; q < 4; q++) {
                    const int s = ptid + 128 * q;
                    const uint32_t d = (uint32_t)((c2 % 3) * BUFSZ + (s >> 3) * 144 + (s & 7) * 16);
                    cp16(sb + OFF_BH + d, H + s);
                    cp16(sb + OFF_BL + d, L + s);
                }
                CP_COMMIT();
            }
            // prefetch A[gi+1]
            if (gi + 1 < NCHT) {
                const int c = gi + 1;
                const int m2 = c >> 4, cc = c & 15;
                const float* X = (m2 == 0) ? xTF : ((m2 == 1) ? xDE : xFFT);
                const float* p = X + (rowbase + prow) * DIMK + cc * KC + pcb;
                n0 = *reinterpret_cast<const float4*>(p);
                n1 = *reinterpret_cast<const float4*>(p + 4);
                n2 = *reinterpret_cast<const float4*>(p + 8);
                n3 = *reinterpret_cast<const float4*>(p + 12);
            }
            // split + store A[gi] into stage st
            {
                unsigned char* bp = smemc + st * BUFSZ;
                uint4 hi, lo;
                split8(a0, a1, hi, lo);
                *reinterpret_cast<uint4*>(bp + OFF_AH + aoff)      = hi;
                *reinterpret_cast<uint4*>(bp + OFF_AL + aoff)      = lo;
                split8(a2, a3, hi, lo);
                *reinterpret_cast<uint4*>(bp + OFF_AH + aoff + 16) = hi;
                *reinterpret_cast<uint4*>(bp + OFF_AL + aoff + 16) = lo;
                x2acc += sq8(a0, a1) + sq8(a2, a3);
            }
            // ensure B[gi] landed (pending groups = issued_upto - gi)
            if (gi + 2 < NCHT)      CP_WAIT2();
            else if (gi + 1 < NCHT) CP_WAIT1();
            else                    CP_WAIT0();
            BARRV(BID_FULL + st, 256);
            a0 = n0; a1 = n1; a2 = n2; a3 = n3;

            if ((gi & 15) == 15) {
                float x2t = x2acc;
                x2t += __shfl_xor_sync(0xffffffffu, x2t, 1);
                x2t += __shfl_xor_sync(0xffffffffu, x2t, 2);
                if ((ptid & 3) == 0) sX2[prow] = x2t;
                const int m = gi >> 4;
                if (ptid < 64) { sP2[ptid] = g_p2[m][ptid]; sRv[ptid] = g_rvar[m][ptid]; }
                x2acc = 0.0f;
                BARRV(BID_X2, 256);
            }
        }
    } else {
        // ==================== CONSUMER (warps 0-3) ====================
        const int w  = warp;                        // col block of 16
        const int gr = lane >> 2;
        const int lk = (lane & 3) * 2;
        const uint32_t aP = (uint32_t)(((lane & 15) * A_STR + (lane >> 4) * 8) * 2);
        const uint32_t bP = (uint32_t)(((w * 16 + ((lane >> 3) >> 1) * 8 + (lane & 7)) * A_STR
                                        + ((lane >> 3) & 1) * 8) * 2);
        const int crow = tid >> 2;                  // softmax row
        const int ccb  = (tid & 3) * 16;            // softmax col base
        float acc[2][2][4];
        #pragma unroll
        for (int i = 0; i < 2; i++)
            #pragma unroll
            for (int j = 0; j < 2; j++)
                #pragma unroll
                for (int k = 0; k < 4; k++) acc[i][j][k] = 0.0f;
        float lossAcc = 0.0f;

        for (int gi = 0; gi < NCHT; gi++) {
            const int st = gi % 3;
            BSYNC(BID_FULL + st, 256);
            const uint32_t base = sb + (uint32_t)(st * BUFSZ);

            // 4 k-steps, fragments software-pipelined
            uint32_t fa[2][16], fb[2][8];
            ldsm4(fa[0],      base + OFF_AH + aP);
            ldsm4(fa[0] + 4,  base + OFF_AH + 2304 + aP);
            ldsm4(fa[0] + 8,  base + OFF_AL + aP);
            ldsm4(fa[0] + 12, base + OFF_AL + 2304 + aP);
            ldsm4(fb[0],      base + OFF_BH + bP);
            ldsm4(fb[0] + 4,  base + OFF_BL + bP);
            #pragma unroll
            for (int ks = 0; ks < 4; ks++) {
                const int cur = ks & 1, nxt = cur ^ 1;
                if (ks < 3) {
                    const uint32_t ko = (uint32_t)((ks + 1) * 32);
                    ldsm4(fa[nxt],      base + OFF_AH + aP + ko);
                    ldsm4(fa[nxt] + 4,  base + OFF_AH + 2304 + aP + ko);
                    ldsm4(fa[nxt] + 8,  base + OFF_AL + aP + ko);
                    ldsm4(fa[nxt] + 12, base + OFF_AL + 2304 + aP + ko);
                    ldsm4(fb[nxt],      base + OFF_BH + bP + ko);
                    ldsm4(fb[nxt] + 4,  base + OFF_BL + bP + ko);
                }
                const uint32_t* ah0 = fa[cur];
                const uint32_t* ah1 = fa[cur] + 4;
                const uint32_t* al0 = fa[cur] + 8;
                const uint32_t* al1 = fa[cur] + 12;
                const uint32_t* bh  = fb[cur];
                const uint32_t* bl  = fb[cur] + 4;
                mma_bf16(acc[0][0], ah0, bh);
                mma_bf16(acc[1][0], ah1, bh);
                mma_bf16(acc[0][1], ah0, bh + 2);
                mma_bf16(acc[1][1], ah1, bh + 2);
                mma_bf16(acc[0][0], ah0, bl);
                mma_bf16(acc[1][0], ah1, bl);
                mma_bf16(acc[0][1], ah0, bl + 2);
                mma_bf16(acc[1][1], ah1, bl + 2);
                mma_bf16(acc[0][0], al0, bh);
                mma_bf16(acc[1][0], al1, bh);
                mma_bf16(acc[0][1], al0, bh + 2);
                mma_bf16(acc[1][1], al1, bh + 2);
            }

            if ((gi & 15) != 15) {
                BARRV(BID_EMPTY + st, 256);
            } else {
                const int m = gi >> 4;
                BSYNC(BID_X2, 256);                 // x2 / p2 / rvar published
                // logits -> sL
                #pragma unroll
                for (int mt = 0; mt < 2; mt++) {
                    const int r0 = mt * 16 + gr;
                    const float x2a = sX2[r0], x2b = sX2[r0 + 8];
                    #pragma unroll
                    for (int nh = 0; nh < 2; nh++) {
                        const int c0 = w * 16 + nh * 8 + lk;
                        const float p20 = sP2[c0], p21 = sP2[c0 + 1];
                        const float rv0 = sRv[c0], rv1 = sRv[c0 + 1];
                        const float* A = acc[mt][nh];
                        sL[r0 * SL_STR + c0]           = fmaf(2.0f, A[0], -(x2a + p20)) * rv0;
                        sL[r0 * SL_STR + c0 + 1]       = fmaf(2.0f, A[1], -(x2a + p21)) * rv1;
                        sL[(r0 + 8) * SL_STR + c0]     = fmaf(2.0f, A[2], -(x2b + p20)) * rv0;
                        sL[(r0 + 8) * SL_STR + c0 + 1] = fmaf(2.0f, A[3], -(x2b + p21)) * rv1;
                    }
                }
                BSYNC(BID_CONS, 128);               // consumer-only
                // softmax: 4 threads/row, 16 cols each
                {
                    const float* Lr = sL + crow * SL_STR;
                    float f[16];
                    #pragma unroll
                    for (int i = 0; i < 16; i++) f[i] = Lr[ccb + i];
                    const float Ly = Lr[cls];

                    float mx = f[0];
                    #pragma unroll
                    for (int i = 1; i < 16; i++) mx = fmaxf(mx, f[i]);
                    mx = fmaxf(mx, __shfl_xor_sync(0xffffffffu, mx, 1));
                    mx = fmaxf(mx, __shfl_xor_sync(0xffffffffu, mx, 2));

                    float s = 0.0f;
                    #pragma unroll
                    for (int i = 0; i < 16; i++) { f[i] = __expf(f[i] - mx); s += f[i]; }
                    s += __shfl_xor_sync(0xffffffffu, s, 1);
                    s += __shfl_xor_sync(0xffffffffu, s, 2);

                    const float winv = wts[m] / s;
                    float* pr = sPrd + crow * PRED_STR + ccb;
                    #pragma unroll
                    for (int i = 0; i < 16; i++) pr[i] += f[i] * winv;

                    if ((tid & 3) == (cls >> 4))
                        lossAcc += -wts[m] * (Ly - mx - logf(s));
                }
                BARRV(BID_EMPTY + st, 256);         // free stage after epilogue
                #pragma unroll
                for (int i = 0; i < 2; i++)
                    #pragma unroll
                    for (int j = 0; j < 2; j++)
                        #pragma unroll
                        for (int k = 0; k < 4; k++) acc[i][j][k] = 0.0f;
            }
        }

        // ---- final: argmax over fused preds + reduction (consumers) ----
        {
            const float* pr = sPrd + crow * PRED_STR + ccb;
            float bv = pr[0]; int bi = ccb;
            #pragma unroll
            for (int i = 1; i < 16; i++)
                if (pr[i] > bv) { bv = pr[i]; bi = ccb + i; }
            #pragma unroll
            for (int o = 1; o <= 2; o <<= 1) {
                const float ov = __shfl_xor_sync(0xffffffffu, bv, o);
                const int   oi = __shfl_xor_sync(0xffffffffu, bi, o);
                if (ov > bv || (ov == bv && oi < bi)) { bv = ov; bi = oi; }
            }
            float ls = lossAcc;
            ls += __shfl_xor_sync(0xffffffffu, ls, 1);
            ls += __shfl_xor_sync(0xffffffffu, ls, 2);

            float lrow = ((lane & 3) == 0) ? ls : 0.0f;
            int   arw  = ((lane & 3) == 0 && bi == cls) ? 1 : 0;
            lrow += __shfl_xor_sync(0xffffffffu, lrow, 4);
            lrow += __shfl_xor_sync(0xffffffffu, lrow, 8);
            lrow += __shfl_xor_sync(0xffffffffu, lrow, 16);
            arw  += __shfl_xor_sync(0xffffffffu, arw, 4);
            arw  += __shfl_xor_sync(0xffffffffu, arw, 8);
            arw  += __shfl_xor_sync(0xffffffffu, arw, 16);
            if (lane == 0) {
                atomicAdd(sBL, lrow);
                atomicAdd(sBA, arw);
            }
        }
    }

    __syncthreads();
    if (tid == 0) {
        g_part[blockIdx.x] = make_float2(*sBL, (float)*sBA);
        __threadfence();
        const int v = atomicAdd(&g_done, 1);
        sLast = (v == NCTA - 1) ? 1 : 0;
    }
    __syncthreads();

    if (sLast) {
        float2 p = g_part[tid];
        float l = p.x, a = p.y;
        #pragma unroll
        for (int o = 16; o > 0; o >>= 1) {
            l += __shfl_xor_sync(0xffffffffu, l, o);
            a += __shfl_xor_sync(0xffffffffu, a, o);
        }
        float* rl = sX2;
        float* ra = sX2 + 8;
        if ((tid & 31) == 0) { rl[warp] = l; ra[warp] = a; }
        __syncthreads();
        if (tid == 0) {
            float ls = 0.0f, as = 0.0f;
            #pragma unroll
            for (int i = 0; i < 8; i++) { ls += rl[i]; as += ra[i]; }
            out[0] = ls * (1.0f / NROWS);
            if (out_size > 1) out[1] = as * (1.0f / NROWS);
            for (int i = 2; i < out_size; i++) out[i] = 0.0f;
            g_done = 0;
        }
    }
}

// ---------------------------------------------------------------------------
extern "C" void kernel_launch(void* const* d_in, const int* in_sizes, int n_in,
                              void* d_out, int out_size)
{
    (void)in_sizes; (void)n_in;
    const float* TFq  = (const float*)d_in[0];
    const float* pTF  = (const float*)d_in[1];
    const float* vTF  = (const float*)d_in[2];
    const float* DEq  = (const float*)d_in[3];
    const float* pDE  = (const float*)d_in[4];
    const float* vDE  = (const float*)d_in[5];
    const float* FFTq = (const float*)d_in[6];
    const float* pFFT = (const float*)d_in[7];
    const float* vFFT = (const float*)d_in[8];

    static int smem_set = 0;
    if (!smem_set) {
        cudaFuncSetAttribute(fusion_kernel, cudaFuncAttributeMaxDynamicSharedMemorySize, SMEM_TOTAL);
        smem_set = 1;
    }

    prep_kernel<<<192, 128>>>(pTF, vTF, pDE, vDE, pFFT, vFFT);
    fusion_kernel<<<NCTA, 256, SMEM_TOTAL>>>(TFq, DEq, FFTq, (float*)d_out, out_size);
}

// round 15
// speedup vs baseline: 1.8543x; 1.8543x over previous
#include <cuda_runtime.h>
#include <cuda_bf16.h>
#include <stdint.h>

#define KCLS   64
#define QPC    128
#define DIMK   1024
#define NROWS  (KCLS * QPC)      // 8192
#define TMR    32                // rows per CTA
#define NCTA   (NROWS / TMR)     // 256
#define KC     64                // k elems per chunk
#define NCHUNK (DIMK / KC)       // 16 per modality

// ---------------- smem layout (bytes), stride-72 bf16 rows (144B) -----------
#define A_STR   72
#define OFF_AH  0
#define OFF_AL  4608
#define OFF_BH  9216
#define OFF_BL  18432
#define BUFSZ   27648
#define NSTAGE  3
// k-partial xp buffers (4 x 32x66 fp32 = 4 x 8448B) live inside stage0/1,
// used only during the per-modality epilogue (pipeline drained there).
#define PART_STR 66
#define PART_SZ  8448
#define OFF_SX2 (NSTAGE * BUFSZ)             // 82944
#define OFF_SP2 (OFF_SX2 + 128)
#define OFF_SRV (OFF_SP2 + 256)
#define OFF_RED (OFF_SRV + 256)
#define SMEM_TOTAL (OFF_RED + 64)            // 74432 -> 2 CTAs/SM

__device__ float  g_p2[3][KCLS];
__device__ float  g_rvar[3][KCLS];
__device__ float2 g_part[NCTA];
__device__ int    g_done;
// pre-split protos: [m][chunk(16)][row(64)][8 uint4]  (row = 64 bf16 = 128 B)
__device__ uint4  g_Bh2[3 * NCHUNK * KCLS * 8];
__device__ uint4  g_Bl2[3 * NCHUNK * KCLS * 8];

// ---------------------------------------------------------------------------
__device__ __forceinline__ uint32_t smem_u32(const void* p) {
    uint32_t a;
    asm("{ .reg .u64 t; cvta.to.shared.u64 t, %1; cvt.u32.u64 %0, t; }" : "=r"(a) : "l"(p));
    return a;
}
__device__ __forceinline__ void cp16(uint32_t dst, const void* src) {
    asm volatile("cp.async.cg.shared.global [%0], [%1], 16;" :: "r"(dst), "l"(src) : "memory");
}
#define CP_COMMIT() asm volatile("cp.async.commit_group;" ::: "memory")
#define CP_WAIT0()  asm volatile("cp.async.wait_group 0;" ::: "memory")
#define CP_WAIT1()  asm volatile("cp.async.wait_group 1;" ::: "memory")

__device__ __forceinline__ void ldsm4(uint32_t* r, uint32_t a) {
    asm volatile("ldmatrix.sync.aligned.m8n8.x4.shared.b16 {%0,%1,%2,%3}, [%4];"
                 : "=r"(r[0]), "=r"(r[1]), "=r"(r[2]), "=r"(r[3]) : "r"(a));
}
__device__ __forceinline__ void mma_bf16(float c[4], const uint32_t a[4], const uint32_t b[2]) {
    asm volatile(
        "mma.sync.aligned.m16n8k16.row.col.f32.bf16.bf16.f32 "
        "{%0,%1,%2,%3}, {%4,%5,%6,%7}, {%8,%9}, {%0,%1,%2,%3};\n"
        : "+f"(c[0]), "+f"(c[1]), "+f"(c[2]), "+f"(c[3])
        : "r"(a[0]), "r"(a[1]), "r"(a[2]), "r"(a[3]), "r"(b[0]), "r"(b[1]));
}

// fp32x8 -> bf16 hi + bf16 lo
__device__ __forceinline__ void split8(float4 a, float4 b, uint4& hi, uint4& lo) {
    float f[8] = {a.x, a.y, a.z, a.w, b.x, b.y, b.z, b.w};
    uint32_t hw[4], lw[4];
    #pragma unroll
    for (int i = 0; i < 4; i++) {
        __nv_bfloat162 h = __floats2bfloat162_rn(f[2*i], f[2*i+1]);
        float r0 = f[2*i]     - __bfloat162float(h.x);
        float r1 = f[2*i + 1] - __bfloat162float(h.y);
        __nv_bfloat162 l = __floats2bfloat162_rn(r0, r1);
        hw[i] = *reinterpret_cast<uint32_t*>(&h);
        lw[i] = *reinterpret_cast<uint32_t*>(&l);
    }
    hi = make_uint4(hw[0], hw[1], hw[2], hw[3]);
    lo = make_uint4(lw[0], lw[1], lw[2], lw[3]);
}
__device__ __forceinline__ float sq8(float4 a, float4 b) {
    return a.x*a.x + a.y*a.y + a.z*a.z + a.w*a.w
         + b.x*b.x + b.y*b.y + b.z*b.z + b.w*b.w;
}

// ---------------------------------------------------------------------------
// prep: p2, 1/var, pre-split protos into chunk-major bf16 hi/lo (KC=64 rows)
// ---------------------------------------------------------------------------
__global__ void prep_kernel(const float* __restrict__ pTF, const float* __restrict__ vTF,
                            const float* __restrict__ pDE, const float* __restrict__ vDE,
                            const float* __restrict__ pFFT, const float* __restrict__ vFFT)
{
    __shared__ float red[4];
    const int b = blockIdx.x;
    const int m = b >> 6, j = b & 63;
    const int tid = threadIdx.x;

    const float* P = (m == 0 ? pTF : (m == 1 ? pDE : pFFT)) + (size_t)j * DIMK;
    const int c0 = tid * 8;
    float4 x0 = *reinterpret_cast<const float4*>(P + c0);
    float4 x1 = *reinterpret_cast<const float4*>(P + c0 + 4);
    float s = sq8(x0, x1);

    uint4 hi, lo; split8(x0, x1, hi, lo);
    const int chunk = c0 >> 6;
    const int col   = c0 & 63;
    const size_t idx = (((size_t)(m * NCHUNK + chunk) * KCLS) + j) * 8 + (col >> 3);
    g_Bh2[idx] = hi;
    g_Bl2[idx] = lo;

    #pragma unroll
    for (int o = 16; o > 0; o >>= 1) s += __shfl_xor_sync(0xffffffffu, s, o);
    if ((tid & 31) == 0) red[tid >> 5] = s;
    __syncthreads();
    if (tid == 0) {
        g_p2[m][j] = red[0] + red[1] + red[2] + red[3];
        const float* V = (m == 0 ? vTF : (m == 1 ? vDE : vFFT));
        g_rvar[m][j] = 1.0f / V[j];
    }
}

// ---------------------------------------------------------------------------
// fused kernel: 3-stage cp.async ring + m32n32 warp tiles with 4-way k-split
// bf16 hi/lo HMMA, inline-logit softmax/loss/argmax, last-CTA reduction.
// 256 CTAs x 256 threads; warp w -> (kh = w>>1, wn = w&1).
// ---------------------------------------------------------------------------
__global__ void __launch_bounds__(256, 2)
fusion_kernel(const float* __restrict__ xTF, const float* __restrict__ xDE,
              const float* __restrict__ xFFT, float* __restrict__ out, int out_size)
{
    extern __shared__ unsigned char smemc[];
    __shared__ int sLast;
    const uint32_t sb = smem_u32(smemc);

    const int tid  = threadIdx.x;
    const int warp = tid >> 5;
    const int lane = tid & 31;
    const int kh   = warp >> 1;            // k-step 0..3 within chunk
    const int wn   = warp & 1;             // col block of 32
    const int gr   = lane >> 2;
    const int lk   = (lane & 3) * 2;
    const int cls  = (int)(blockIdx.x >> 2);
    const size_t rowbase = (size_t)blockIdx.x * TMR;

    // producer mappings (A): 8 threads/row, 8 floats each
    const int arow  = tid >> 3;
    const int acseg = (tid & 7) * 8;

    float* sX2  = reinterpret_cast<float*>(smemc + OFF_SX2);
    float* sP2  = reinterpret_cast<float*>(smemc + OFF_SP2);
    float* sRv  = reinterpret_cast<float*>(smemc + OFF_SRV);
    float* sBL  = reinterpret_cast<float*>(smemc + OFF_RED);
    int*   sBA  = reinterpret_cast<int*>(smemc + OFF_RED + 4);

    if (tid == 0) { *sBL = 0.0f; *sBA = 0; }

    const uint32_t aoff = (uint32_t)(arow * 144 + acseg * 2);
    // ldmatrix address parts (per-warp constant, incl. k-step offset kh*32B)
    const uint32_t ko  = (uint32_t)(kh * 32);
    const uint32_t aP  = (uint32_t)(((lane & 15) * A_STR + (lane >> 4) * 8) * 2) + ko;
    const uint32_t bP  = (uint32_t)(((wn * 32 + ((lane >> 3) >> 1) * 8 + (lane & 7)) * A_STR
                                     + ((lane >> 3) & 1) * 8) * 2) + ko;

    const float* xs[3]  = {xTF, xDE, xFFT};
    const float  wts[3] = {1.0f, 0.8f, 0.6f};

    float pred[8];
    #pragma unroll
    for (int i = 0; i < 8; i++) pred[i] = 0.0f;
    float lossAcc = 0.0f;
    const int lc = (tid & 7) * 8;
    const int lr = tid >> 3;

    for (int m = 0; m < 3; m++) {
        if (tid < 64) { sP2[tid] = g_p2[m][tid]; sRv[tid] = g_rvar[m][tid]; }

        const float* aptr = xs[m] + (rowbase + arow) * DIMK + acseg;
        const uint4* gH = g_Bh2 + (size_t)m * NCHUNK * (KCLS * 8);
        const uint4* gL = g_Bl2 + (size_t)m * NCHUNK * (KCLS * 8);

        float x2acc = 0.0f;
        float acc[2][4][4];
        #pragma unroll
        for (int i = 0; i < 2; i++)
            #pragma unroll
            for (int j = 0; j < 4; j++)
                #pragma unroll
                for (int k = 0; k < 4; k++) acc[i][j][k] = 0.0f;

        // ---- prologue: B[0]->stage0, B[1]->stage1 (2 groups), A[0]->stage0 ----
        {
            #pragma unroll
            for (int q = 0; q < 2; q++) {
                const int s = tid + 256 * q;
                const uint32_t d = (uint32_t)((s >> 3) * 144 + (s & 7) * 16);
                cp16(sb + OFF_BH + d, gH + s);
                cp16(sb + OFF_BL + d, gL + s);
            }
            CP_COMMIT();
            #pragma unroll
            for (int q = 0; q < 2; q++) {
                const int s = tid + 256 * q;
                const uint32_t d = (uint32_t)(BUFSZ + (s >> 3) * 144 + (s & 7) * 16);
                cp16(sb + OFF_BH + d, gH + (KCLS * 8) + s);
                cp16(sb + OFF_BL + d, gL + (KCLS * 8) + s);
            }
            CP_COMMIT();

            float4 a0 = *reinterpret_cast<const float4*>(aptr);
            float4 a1 = *reinterpret_cast<const float4*>(aptr + 4);
            x2acc += sq8(a0, a1);
            uint4 hi, lo;
            split8(a0, a1, hi, lo);
            *reinterpret_cast<uint4*>(smemc + OFF_AH + aoff) = hi;
            *reinterpret_cast<uint4*>(smemc + OFF_AL + aoff) = lo;

            CP_WAIT1();          // B[0] landed; B[1] still in flight
            __syncthreads();
        }

        for (int ci = 0; ci < NCHUNK; ci++) {
            const int st  = ci % NSTAGE;
            const uint32_t base = sb + (uint32_t)(st * BUFSZ);
            const bool hn1 = (ci + 1 < NCHUNK);
            const bool hn2 = (ci + 2 < NCHUNK);

            // 1. issue B copies for ci+2 into stage (ci+2)%3
            if (hn2) {
                const int st2 = (ci + 2) % NSTAGE;
                const uint4* nH = gH + (size_t)(ci + 2) * (KCLS * 8);
                const uint4* nL = gL + (size_t)(ci + 2) * (KCLS * 8);
                #pragma unroll
                for (int q = 0; q < 2; q++) {
                    const int s = tid + 256 * q;
                    const uint32_t d = (uint32_t)(st2 * BUFSZ + (s >> 3) * 144 + (s & 7) * 16);
                    cp16(sb + OFF_BH + d, nH + s);
                    cp16(sb + OFF_BL + d, nL + s);
                }
                CP_COMMIT();
            }

            // 2. A prefetch for ci+1 (LDG into regs)
            float4 na0, na1;
            if (hn1) {
                const float* ap = aptr + (ci + 1) * KC;
                na0 = *reinterpret_cast<const float4*>(ap);
                na1 = *reinterpret_cast<const float4*>(ap + 4);
            }

            // 3. MMA: this warp's single k-step, m32 x n32 tile
            {
                uint32_t ah[8], al[8], bh[8], bl[8];
                ldsm4(ah,     base + OFF_AH + aP);
                ldsm4(ah + 4, base + OFF_AH + 2304 + aP);
                ldsm4(al,     base + OFF_AL + aP);
                ldsm4(al + 4, base + OFF_AL + 2304 + aP);
                ldsm4(bh,     base + OFF_BH + bP);
                ldsm4(bh + 4, base + OFF_BH + 2304 + bP);
                ldsm4(bl,     base + OFF_BL + bP);
                ldsm4(bl + 4, base + OFF_BL + 2304 + bP);
                // term-major ordering: same acc revisited at distance 8
                #pragma unroll
                for (int mt = 0; mt < 2; mt++)
                    #pragma unroll
                    for (int nt = 0; nt < 4; nt++)
                        mma_bf16(acc[mt][nt], ah + mt * 4, bh + nt * 2);
                #pragma unroll
                for (int mt = 0; mt < 2; mt++)
                    #pragma unroll
                    for (int nt = 0; nt < 4; nt++)
                        mma_bf16(acc[mt][nt], ah + mt * 4, bl + nt * 2);
                #pragma unroll
                for (int mt = 0; mt < 2; mt++)
                    #pragma unroll
                    for (int nt = 0; nt < 4; nt++)
                        mma_bf16(acc[mt][nt], al + mt * 4, bh + nt * 2);
            }

            // 4. convert + store A[ci+1] into stage (ci+1)%3
            if (hn1) {
                const uint32_t nb = (uint32_t)(((ci + 1) % NSTAGE) * BUFSZ);
                x2acc += sq8(na0, na1);
                uint4 hi, lo;
                split8(na0, na1, hi, lo);
                *reinterpret_cast<uint4*>(smemc + nb + OFF_AH + aoff) = hi;
                *reinterpret_cast<uint4*>(smemc + nb + OFF_AL + aoff) = lo;
            }

            // 5. ensure B[ci+1] landed
            if (hn2) CP_WAIT1(); else CP_WAIT0();
            // 6. publish
            __syncthreads();
        }

        // ---- reduce x2 (8 threads/row) ----
        {
            float x2t = x2acc;
            x2t += __shfl_xor_sync(0xffffffffu, x2t, 1);
            x2t += __shfl_xor_sync(0xffffffffu, x2t, 2);
            x2t += __shfl_xor_sync(0xffffffffu, x2t, 4);
            if ((tid & 7) == 0) sX2[arow] = x2t;
        }
        __syncthreads();   // mainloop reads done; stages now reusable as partial bufs

        // ---- write k-partials: warp (kh, wn) -> buffer kh, cols wn*32.. ----
        {
            float* Pk = reinterpret_cast<float*>(smemc + kh * PART_SZ);
            #pragma unroll
            for (int mt = 0; mt < 2; mt++) {
                const int r0 = mt * 16 + gr;
                #pragma unroll
                for (int nt = 0; nt < 4; nt++) {
                    const int c0 = wn * 32 + nt * 8 + lk;
                    *reinterpret_cast<float2*>(&Pk[r0 * PART_STR + c0]) =
                        make_float2(acc[mt][nt][0], acc[mt][nt][1]);
                    *reinterpret_cast<float2*>(&Pk[(r0 + 8) * PART_STR + c0]) =
                        make_float2(acc[mt][nt][2], acc[mt][nt][3]);
                }
            }
        }
        __syncthreads();

        // ---- softmax per row (8 threads/row, 8-col stripes), logits inline ----
        {
            const float* P0 = reinterpret_cast<float*>(smemc);
            const float* P1 = reinterpret_cast<float*>(smemc + PART_SZ);
            const float* P2 = reinterpret_cast<float*>(smemc + 2 * PART_SZ);
            const float* P3 = reinterpret_cast<float*>(smemc + 3 * PART_SZ);
            const int rb = lr * PART_STR;
            const float x2 = sX2[lr];

            float f[8];
            float Ly = 0.0f;
            #pragma unroll
            for (int i = 0; i < 8; i++) {
                const int c = lc + i;
                const float xp = P0[rb + c] + P1[rb + c] + P2[rb + c] + P3[rb + c];
                f[i] = fmaf(2.0f, xp, -(x2 + sP2[c])) * sRv[c];
                if (c == cls) Ly = f[i];
            }

            float mx = f[0];
            #pragma unroll
            for (int i = 1; i < 8; i++) mx = fmaxf(mx, f[i]);
            mx = fmaxf(mx, __shfl_xor_sync(0xffffffffu, mx, 1));
            mx = fmaxf(mx, __shfl_xor_sync(0xffffffffu, mx, 2));
            mx = fmaxf(mx, __shfl_xor_sync(0xffffffffu, mx, 4));

            float s = 0.0f;
            #pragma unroll
            for (int i = 0; i < 8; i++) { f[i] = __expf(f[i] - mx); s += f[i]; }
            s += __shfl_xor_sync(0xffffffffu, s, 1);
            s += __shfl_xor_sync(0xffffffffu, s, 2);
            s += __shfl_xor_sync(0xffffffffu, s, 4);

            const float winv = wts[m] / s;
            #pragma unroll
            for (int i = 0; i < 8; i++) pred[i] += f[i] * winv;

            if ((tid & 7) == (cls >> 3))
                lossAcc += -wts[m] * (Ly - mx - logf(s));
        }
        __syncthreads();   // partial reads done before next modality's prologue
    }

    // ---- final: argmax + block reduction ----
    {
        float bv = pred[0]; int bi = lc;
        #pragma unroll
        for (int i = 1; i < 8; i++)
            if (pred[i] > bv) { bv = pred[i]; bi = lc + i; }
        #pragma unroll
        for (int o = 1; o <= 4; o <<= 1) {
            const float ov = __shfl_xor_sync(0xffffffffu, bv, o);
            const int   oi = __shfl_xor_sync(0xffffffffu, bi, o);
            if (ov > bv || (ov == bv && oi < bi)) { bv = ov; bi = oi; }
        }
        float ls = lossAcc;
        ls += __shfl_xor_sync(0xffffffffu, ls, 1);
        ls += __shfl_xor_sync(0xffffffffu, ls, 2);
        ls += __shfl_xor_sync(0xffffffffu, ls, 4);

        float lrow = ((lane & 7) == 0) ? ls : 0.0f;
        int   arw  = ((lane & 7) == 0 && bi == cls) ? 1 : 0;
        lrow += __shfl_xor_sync(0xffffffffu, lrow, 8);
        lrow += __shfl_xor_sync(0xffffffffu, lrow, 16);
        arw  += __shfl_xor_sync(0xffffffffu, arw, 8);
        arw  += __shfl_xor_sync(0xffffffffu, arw, 16);
        if (lane == 0) {
            atomicAdd(sBL, lrow);
            atomicAdd(sBA, arw);
        }
    }
    __syncthreads();
    if (tid == 0) {
        g_part[blockIdx.x] = make_float2(*sBL, (float)*sBA);
        __threadfence();
        const int v = atomicAdd(&g_done, 1);
        sLast = (v == NCTA - 1) ? 1 : 0;
    }
    __syncthreads();

    if (sLast) {
        float2 p = g_part[tid];
        float l = p.x, a = p.y;
        #pragma unroll
        for (int o = 16; o > 0; o >>= 1) {
            l += __shfl_xor_sync(0xffffffffu, l, o);
            a += __shfl_xor_sync(0xffffffffu, a, o);
        }
        float* rl = sX2;
        float* ra = sX2 + 8;
        if ((tid & 31) == 0) { rl[warp] = l; ra[warp] = a; }
        __syncthreads();
        if (tid == 0) {
            float ls = 0.0f, as = 0.0f;
            #pragma unroll
            for (int i = 0; i < 8; i++) { ls += rl[i]; as += ra[i]; }
            out[0] = ls * (1.0f / NROWS);
            if (out_size > 1) out[1] = as * (1.0f / NROWS);
            for (int i = 2; i < out_size; i++) out[i] = 0.0f;
            g_done = 0;
        }
    }
}

// ---------------------------------------------------------------------------
extern "C" void kernel_launch(void* const* d_in, const int* in_sizes, int n_in,
                              void* d_out, int out_size)
{
    (void)in_sizes; (void)n_in;
    const float* TFq  = (const float*)d_in[0];
    const float* pTF  = (const float*)d_in[1];
    const float* vTF  = (const float*)d_in[2];
    const float* DEq  = (const float*)d_in[3];
    const float* pDE  = (const float*)d_in[4];
    const float* vDE  = (const float*)d_in[5];
    const float* FFTq = (const float*)d_in[6];
    const float* pFFT = (const float*)d_in[7];
    const float* vFFT = (const float*)d_in[8];

    static int smem_set = 0;
    if (!smem_set) {
        cudaFuncSetAttribute(fusion_kernel, cudaFuncAttributeMaxDynamicSharedMemorySize, SMEM_TOTAL);
        smem_set = 1;
    }

    prep_kernel<<<192, 128>>>(pTF, vTF, pDE, vDE, pFFT, vFFT);
    fusion_kernel<<<NCTA, 256, SMEM_TOTAL>>>(TFq, DEq, FFTq, (float*)d_out, out_size);
}